// round 12
// baseline (speedup 1.0000x reference)
#include <cuda_runtime.h>

// SmartDerivatives R12 = R11 structure + LDG.128 pair-of-descs loading.
// R6/R11 were pinned at ~3.7TB/s by L1tex wavefronts: stride-24B LDG.64 x3
// delivers each 128B line of `left` ~3x (38 wavefronts / 64 descs). Here each
// lane owns TWO consecutive descs = 48B = 3 aligned float4 loads
// (12 wavefronts / 64 descs). Odd row starts/lengths are peeled (1 desc via
// float2 path). Topology unchanged: 320 thr, mirrored row pairs, i-side shfl
// reduction, j-side warp-private bins, __ldcs streaming on left.

constexpr int NA    = 100;
constexpr int D     = 4950;
constexpr int E     = D * 6;
constexpr int S3    = NA * 3;        // 300
constexpr int WARPS = 10;
constexpr int T     = WARPS * 32;    // 320

// single-desc (peel) path: desc*24B is always 8B-aligned
__device__ __forceinline__ void one_desc(
    int desc, int j, const float* __restrict__ lb, const float* __restrict__ xb,
    float& r0, float& r1, float& r2, float* __restrict__ ca)
{
    const float2* lp = reinterpret_cast<const float2*>(lb + desc * 6);
    const float2 l01 = __ldcs(lp);
    const float2 l23 = __ldcs(lp + 1);
    const float2 l45 = __ldcs(lp + 2);
    const float  xv  = __ldg(xb + desc);
    r0 = fmaf(l01.x, xv, r0);
    r1 = fmaf(l01.y, xv, r1);
    r2 = fmaf(l23.x, xv, r2);
    float* cj = ca + j * 3;
    cj[0] += l23.y * xv;
    cj[1] += l45.x * xv;
    cj[2] += l45.y * xv;
}

__device__ __forceinline__ void process_row(
    int i, int lane,
    const float* __restrict__ lb, const float* __restrict__ xb,
    float* __restrict__ ca, float* __restrict__ rowout)
{
    const int base = (i * (2 * NA - i - 1)) >> 1;  // row start desc
    int s = base;
    int n = NA - 1 - i;                            // descs in row

    float r0 = 0.0f, r1 = 0.0f, r2 = 0.0f;

    // front peel: make pair start even (16B-aligned float4 base)
    if (s & 1) {
        if (lane == 0) one_desc(s, i + 1, lb, xb, r0, r1, r2, ca);
        ++s; --n;
    }
    const int npair = n >> 1;
    const int jbase = i + 1 + (s - base);          // j of first paired desc

    const float4* __restrict__ lp4 =
        reinterpret_cast<const float4*>(lb + s * 6);

    #pragma unroll 2
    for (int p = lane; p < npair; p += 32) {
        const float4 a = __ldcs(lp4 + 3 * p);       // d0: slots 0..3
        const float4 c = __ldcs(lp4 + 3 * p + 1);   // d0: 4,5 | d1: 0,1
        const float4 e = __ldcs(lp4 + 3 * p + 2);   // d1: slots 2..5
        const float  x0 = __ldg(xb + s + 2 * p);
        const float  x1 = __ldg(xb + s + 2 * p + 1);

        // desc0 = s+2p
        r0 = fmaf(a.x, x0, r0);
        r1 = fmaf(a.y, x0, r1);
        r2 = fmaf(a.z, x0, r2);
        float* cj = ca + (jbase + 2 * p) * 3;
        cj[0] += a.w * x0;
        cj[1] += c.x * x0;
        cj[2] += c.y * x0;

        // desc1 = s+2p+1
        r0 = fmaf(c.z, x1, r0);
        r1 = fmaf(c.w, x1, r1);
        r2 = fmaf(e.x, x1, r2);
        cj[3] += e.y * x1;
        cj[4] += e.z * x1;
        cj[5] += e.w * x1;
    }

    // back peel: odd remaining count
    if (n & 1) {
        const int dlast = s + n - 1;
        if (lane == 31) one_desc(dlast, jbase + (n - 1), lb, xb, r0, r1, r2, ca);
    }

    #pragma unroll
    for (int off = 16; off; off >>= 1) {
        r0 += __shfl_down_sync(0xffffffffu, r0, off);
        r1 += __shfl_down_sync(0xffffffffu, r1, off);
        r2 += __shfl_down_sync(0xffffffffu, r2, off);
    }
    if (lane == 0) {
        rowout[i * 3 + 0] = r0;
        rowout[i * 3 + 1] = r1;
        rowout[i * 3 + 2] = r2;
    }
}

__global__ void __launch_bounds__(T)
smart_derivatives_kernel(const float* __restrict__ x,
                         const float* __restrict__ left,
                         float* __restrict__ out) {
    __shared__ float colacc[WARPS][S3];  // 12 KB: per-warp j-side bins
    __shared__ float rowout[S3];         // 1.2 KB

    const int b    = blockIdx.x;
    const int t    = threadIdx.x;
    const int w    = t >> 5;
    const int lane = t & 31;

    for (int i = t; i < WARPS * S3; i += T) (&colacc[0][0])[i] = 0.0f;
    if (t < S3) rowout[t] = 0.0f;
    __syncthreads();

    const float* __restrict__ lb = left + (size_t)b * E;
    const float* __restrict__ xb = x + (size_t)b * D;
    float* __restrict__ ca = colacc[w];

    // Mirrored pairing per 20-row band: rows (base+w) and (base+19-w).
    for (int base = 0; base < NA - 1; base += 2 * WARPS) {
        const int i1 = base + w;
        const int i2 = base + (2 * WARPS - 1) - w;
        if (i1 < NA - 1) process_row(i1, lane, lb, xb, ca, rowout);
        if (i2 < NA - 1) process_row(i2, lane, lb, xb, ca, rowout);
    }
    __syncthreads();

    if (t < S3) {
        float s = rowout[t];
        #pragma unroll
        for (int ww = 0; ww < WARPS; ++ww) s += colacc[ww][t];
        out[(size_t)b * S3 + t] = s * s;
    }
}

extern "C" void kernel_launch(void* const* d_in, const int* in_sizes, int n_in,
                              void* d_out, int out_size) {
    const float* x    = (const float*)d_in[0];   // [BATCH, D] fp32
    const float* left = (const float*)d_in[1];   // [BATCH*E] fp32
    (void)in_sizes; (void)n_in; (void)out_size;

    float* out = (float*)d_out;                  // [BATCH, 300] fp32
    smart_derivatives_kernel<<<1024, T>>>(x, left, out);
}